// round 9
// baseline (speedup 1.0000x reference)
#include <cuda_runtime.h>
#include <cuda_bf16.h>
#include <math.h>
#include <cstdint>

#define NN 50000
#define NE 800000
#define D  128
#define NEG 0.2f
#define BNEPS 1e-5f
#define SB 196   // scan blocks (196*256 = 50176 >= NN)

// ---------------- static device scratch (no allocations allowed) ----------------
__device__ float g_xl[NN * D];
__device__ float g_xr[NN * D];
__device__ float g_out[NN * D];
__device__ __nv_bfloat16 g_xh[NN * D];
__device__ __nv_bfloat16 g_xlo[NN * D];
__device__ __nv_bfloat16 g_whi[3 * 2 * D * D];   // W^T per layer/matrix: [lm][n][k]
__device__ __nv_bfloat16 g_wlo[3 * 2 * D * D];
__device__ int   g_srcs[NE];
__device__ int   g_off[NN + 1];
__device__ int   g_cur[NN];
__device__ int   g_cnt[NN];
__device__ int   g_part[256];
__device__ float g_colsum[D];
__device__ float g_colsq[D];
__device__ int   g_is64;

// ---------------- edge dtype probe + counter zero (fused) ----------------
__global__ void k_detect_zero(const int* __restrict__ w) {
    int i = blockIdx.x * 256 + threadIdx.x;
    if (i < NN) g_cnt[i] = 0;
    if (i == 0) {
        int allz = 1;
        for (int j = 1; j < 64; j += 2)
            if (w[j] != 0) allz = 0;
        g_is64 = allz;
    }
}

__device__ __forceinline__ int edge_at(const int* __restrict__ w, int pos, int is64) {
    return is64 ? w[(long long)pos * 2] : w[pos];
}

// ---------------- CSR build ----------------
__global__ void k_hist(const int* __restrict__ ei) {
    int e = blockIdx.x * 256 + threadIdx.x;
    if (e < NE) atomicAdd(&g_cnt[edge_at(ei, NE + e, g_is64)], 1);
}

__global__ void k_part() {
    __shared__ int sh[256];
    int tid = threadIdx.x;
    int i = blockIdx.x * 256 + tid;
    int v = (i < NN) ? g_cnt[i] : 0;
    sh[tid] = v;
    __syncthreads();
    for (int o = 128; o > 0; o >>= 1) {
        if (tid < o) sh[tid] += sh[tid + o];
        __syncthreads();
    }
    if (tid == 0) g_part[blockIdx.x] = sh[0];
}

__global__ void k_scanpart() {
    __shared__ int sh[256];
    int tid = threadIdx.x;
    int v = (tid < SB) ? g_part[tid] : 0;
    sh[tid] = v;
    __syncthreads();
    for (int o = 1; o < 256; o <<= 1) {
        int t = (tid >= o) ? sh[tid - o] : 0;
        __syncthreads();
        sh[tid] += t;
        __syncthreads();
    }
    g_part[tid] = sh[tid] - v;
}

__global__ void k_off() {
    __shared__ int sh[256];
    int tid = threadIdx.x;
    int i = blockIdx.x * 256 + tid;
    int v = (i < NN) ? g_cnt[i] : 0;
    sh[tid] = v;
    __syncthreads();
    for (int o = 1; o < 256; o <<= 1) {
        int t = (tid >= o) ? sh[tid - o] : 0;
        __syncthreads();
        sh[tid] += t;
        __syncthreads();
    }
    int excl = sh[tid] - v + g_part[blockIdx.x];
    if (i < NN) {
        g_off[i] = excl;
        g_cur[i] = excl;
        if (i == NN - 1) g_off[NN] = excl + v;
    }
}

__global__ void k_scatter(const int* __restrict__ ei) {
    int e = blockIdx.x * 256 + threadIdx.x;
    if (e < NE) {
        int is64 = g_is64;
        int src = edge_at(ei, e, is64);
        int dst = edge_at(ei, NE + e, is64);
        int pos = atomicAdd(&g_cur[dst], 1);
        g_srcs[pos] = src;
    }
}

// ---------------- conversions (fp32 -> split bf16) ----------------
__device__ __forceinline__ void split2(float a, float b, uint32_t& hi, uint32_t& lo) {
    __nv_bfloat16 ha = __float2bfloat16(a);
    __nv_bfloat16 hb = __float2bfloat16(b);
    __nv_bfloat16 la = __float2bfloat16(a - __bfloat162float(ha));
    __nv_bfloat16 lb = __float2bfloat16(b - __bfloat162float(hb));
    hi = (uint32_t)__bfloat16_as_ushort(ha) | ((uint32_t)__bfloat16_as_ushort(hb) << 16);
    lo = (uint32_t)__bfloat16_as_ushort(la) | ((uint32_t)__bfloat16_as_ushort(lb) << 16);
}

// W^T split: wt[lm][n][k] = W[l][k][n]   (lm = l*2+m; m: 0=Wl, 1=Wr)
__global__ void k_cvt_w(const float* __restrict__ Wl, const float* __restrict__ Wr) {
    int idx = blockIdx.x * 256 + threadIdx.x;
    if (idx >= 3 * 2 * D * D) return;
    int lm = idx >> 14, r = idx & 16383;
    int n = r >> 7, k = r & 127;
    int l = lm >> 1, m = lm & 1;
    const float* W = m ? Wr : Wl;
    float v = W[l * D * D + k * D + n];
    __nv_bfloat16 h = __float2bfloat16(v);
    __nv_bfloat16 lo = __float2bfloat16(v - __bfloat162float(h));
    g_whi[idx] = h;
    g_wlo[idx] = lo;
}

__global__ void k_cvt_x(const float* __restrict__ x) {
    int i = blockIdx.x * 256 + threadIdx.x;  // over NN*64 float2 groups
    if (i >= NN * 64) return;
    float2 v = ((const float2*)x)[i];
    uint32_t hi, lo;
    split2(v.x, v.y, hi, lo);
    ((uint32_t*)g_xh)[i] = hi;
    ((uint32_t*)g_xlo)[i] = lo;
}

// ---------------- tensor-core dual GEMM: smem + ldmatrix + mma.sync ----------------
__device__ __forceinline__ void mma16816(float* c, const uint32_t* a, const uint32_t* b) {
    asm volatile(
        "mma.sync.aligned.m16n8k16.row.col.f32.bf16.bf16.f32 "
        "{%0,%1,%2,%3}, {%4,%5,%6,%7}, {%8,%9}, {%0,%1,%2,%3};"
        : "+f"(c[0]), "+f"(c[1]), "+f"(c[2]), "+f"(c[3])
        : "r"(a[0]), "r"(a[1]), "r"(a[2]), "r"(a[3]), "r"(b[0]), "r"(b[1]));
}

__device__ __forceinline__ void ldsm4(uint32_t* r, uint32_t addr) {
    asm volatile(
        "ldmatrix.sync.aligned.m8n8.x4.shared.b16 {%0,%1,%2,%3}, [%4];"
        : "=r"(r[0]), "=r"(r[1]), "=r"(r[2]), "=r"(r[3]) : "r"(addr));
}

// Tile: 64 rows x 128 cols, one m (xl/xr) per blockIdx.y. 256 threads.
// smem: A_hi[64][256B] @0 (16KB), A_lo @16KB, B_hi @32KB (128nx256B=32KB), B_lo @64KB.
// Total 96KB -> 2 CTAs/SM.
#define GEMM_SMEM 98304

__global__ void __launch_bounds__(256, 2) k_gemm_mma(int l) {
    extern __shared__ __align__(16) char sm[];
    int tid = threadIdx.x;
    int m = blockIdx.y;
    int row0 = blockIdx.x * 64;

    // stage A (x_hi, x_lo): 64 rows x 16 chunks of 16B
    for (int i = tid; i < 1024; i += 256) {
        int r = i >> 4, c = i & 15;
        int gr = row0 + r;
        uint4 vh = make_uint4(0, 0, 0, 0), vl = make_uint4(0, 0, 0, 0);
        if (gr < NN) {
            vh = *(const uint4*)(g_xh + gr * D + c * 8);
            vl = *(const uint4*)(g_xlo + gr * D + c * 8);
        }
        int sc = c ^ (r & 7);
        *(uint4*)(sm + r * 256 + sc * 16) = vh;
        *(uint4*)(sm + 16384 + r * 256 + sc * 16) = vl;
    }
    // stage B (this m only): hi and lo tiles, 128 n-rows x 16 chunks
    for (int i = tid; i < 4096; i += 256) {
        int tile = i >> 11, j = i & 2047;   // tile 0=hi, 1=lo
        int n = j >> 4, c = j & 15;
        const __nv_bfloat16* src = tile ? g_wlo : g_whi;
        uint4 v = *(const uint4*)(src + ((l * 2 + m) * D + n) * D + c * 8);
        int sc = c ^ (n & 7);
        *(uint4*)(sm + 32768 + tile * 32768 + n * 256 + sc * 16) = v;
    }
    __syncthreads();

    int wid = tid >> 5, lane = tid & 31;
    int rg = wid >> 1;          // row group 0..3: rows rg*16..rg*16+15
    int cg = wid & 1;           // col group: colbase 0 / 64
    int colbase = cg * 64;
    uint32_t sbase = (uint32_t)__cvta_generic_to_shared(sm);
    uint32_t sA_h = sbase;
    uint32_t sA_l = sbase + 16384;
    uint32_t sB_h = sbase + 32768;
    uint32_t sB_l = sbase + 65536;

    float acc[8][4];
#pragma unroll
    for (int nt = 0; nt < 8; nt++)
#pragma unroll
        for (int q = 0; q < 4; q++) acc[nt][q] = 0.f;

    // ldmatrix lane address components
    int a_r = (lane & 7) + ((lane >> 3) & 1) * 8;
    int a_c = lane >> 4;
    int b_n = (lane & 7) + (lane >> 4) * 8;
    int b_c = (lane >> 3) & 1;

#pragma unroll
    for (int ks = 0; ks < 8; ks++) {
        uint32_t ah[4], al[4];
        {
            int r = rg * 16 + a_r;
            int c = 2 * ks + a_c;
            uint32_t off = (uint32_t)(r * 256 + ((c ^ (r & 7)) << 4));
            ldsm4(ah, sA_h + off);
            ldsm4(al, sA_l + off);
        }
#pragma unroll
        for (int ng = 0; ng < 4; ng++) {
            int n = colbase + ng * 16 + b_n;
            int c = 2 * ks + b_c;
            uint32_t off = (uint32_t)(n * 256 + ((c ^ (n & 7)) << 4));
            uint32_t bh[4], bl[4];
            ldsm4(bh, sB_h + off);
            ldsm4(bl, sB_l + off);
            mma16816(acc[2 * ng], ah, &bh[0]);
            mma16816(acc[2 * ng], ah, &bl[0]);
            mma16816(acc[2 * ng], al, &bh[0]);
            mma16816(acc[2 * ng + 1], ah, &bh[2]);
            mma16816(acc[2 * ng + 1], ah, &bl[2]);
            mma16816(acc[2 * ng + 1], al, &bh[2]);
        }
    }

    float* dst = m ? g_xr : g_xl;
    int g = lane >> 2, t = lane & 3;
#pragma unroll
    for (int nt = 0; nt < 8; nt++) {
        int r0 = row0 + rg * 16 + g;
        int cc = colbase + nt * 8 + 2 * t;
        if (r0 < NN)
            *(float2*)(dst + r0 * D + cc) = make_float2(acc[nt][0], acc[nt][1]);
        if (r0 + 8 < NN)
            *(float2*)(dst + (r0 + 8) * D + cc) = make_float2(acc[nt][2], acc[nt][3]);
    }
}

// ---------------- per-node GATv2: 8-lane groups, 4 edges in flight ----------------
__device__ __forceinline__ float lrelu(float z) {
    return z > 0.f ? z : NEG * z;
}

__global__ void __launch_bounds__(64) k_node(const float* __restrict__ att,
                                             const float* __restrict__ bias) {
    int node = blockIdx.x * 2 + (threadIdx.x >> 5);
    if (node >= NN) return;
    int lane = threadIdx.x & 31;
    int l8 = lane & 7;      // 16 channels per lane: [l8*16, l8*16+16)
    int grp = lane >> 3;    // group 0..3: edges beg+grp, beg+grp+4, ...
    const unsigned gmask = 0xFFu << (grp << 3);
    int beg = g_off[node], end = g_off[node + 1];

    const float4* xr4 = (const float4*)(g_xr + node * 128 + l8 * 16);
    float4 xr0 = xr4[0], xr1 = xr4[1], xr2 = xr4[2], xr3 = xr4[3];
    const float4* at4 = (const float4*)(att + l8 * 16);
    float4 a0 = at4[0], a1 = at4[1], a2 = at4[2], a3 = at4[3];

    float m = -1e30f, sum = 0.f;
    float4 c0 = make_float4(0.f, 0.f, 0.f, 0.f);
    float4 c1 = make_float4(0.f, 0.f, 0.f, 0.f);
    float4 c2 = make_float4(0.f, 0.f, 0.f, 0.f);
    float4 c3 = make_float4(0.f, 0.f, 0.f, 0.f);

    for (int p = beg + grp; p < end; p += 4) {
        int s = g_srcs[p];
        const float4* v4 = (const float4*)(g_xl + s * 128 + l8 * 16);
        float4 v0 = v4[0], v1 = v4[1], v2 = v4[2], v3 = v4[3];
        float d0 = lrelu(v0.x + xr0.x) * a0.x;
        d0 = fmaf(lrelu(v0.y + xr0.y), a0.y, d0);
        d0 = fmaf(lrelu(v0.z + xr0.z), a0.z, d0);
        d0 = fmaf(lrelu(v0.w + xr0.w), a0.w, d0);
        float d1 = lrelu(v1.x + xr1.x) * a1.x;
        d1 = fmaf(lrelu(v1.y + xr1.y), a1.y, d1);
        d1 = fmaf(lrelu(v1.z + xr1.z), a1.z, d1);
        d1 = fmaf(lrelu(v1.w + xr1.w), a1.w, d1);
        float d2 = lrelu(v2.x + xr2.x) * a2.x;
        d2 = fmaf(lrelu(v2.y + xr2.y), a2.y, d2);
        d2 = fmaf(lrelu(v2.z + xr2.z), a2.z, d2);
        d2 = fmaf(lrelu(v2.w + xr2.w), a2.w, d2);
        float d3 = lrelu(v3.x + xr3.x) * a3.x;
        d3 = fmaf(lrelu(v3.y + xr3.y), a3.y, d3);
        d3 = fmaf(lrelu(v3.z + xr3.z), a3.z, d3);
        d3 = fmaf(lrelu(v3.w + xr3.w), a3.w, d3);
        float d = (d0 + d1) + (d2 + d3);
#pragma unroll
        for (int o = 1; o < 8; o <<= 1) d += __shfl_xor_sync(gmask, d, o);
        float mn = fmaxf(m, d);
        float c = __expf(m - mn);
        float w = __expf(d - mn);
        sum = sum * c + w;
        c0.x = fmaf(c0.x, c, w * v0.x); c0.y = fmaf(c0.y, c, w * v0.y);
        c0.z = fmaf(c0.z, c, w * v0.z); c0.w = fmaf(c0.w, c, w * v0.w);
        c1.x = fmaf(c1.x, c, w * v1.x); c1.y = fmaf(c1.y, c, w * v1.y);
        c1.z = fmaf(c1.z, c, w * v1.z); c1.w = fmaf(c1.w, c, w * v1.w);
        c2.x = fmaf(c2.x, c, w * v2.x); c2.y = fmaf(c2.y, c, w * v2.y);
        c2.z = fmaf(c2.z, c, w * v2.z); c2.w = fmaf(c2.w, c, w * v2.w);
        c3.x = fmaf(c3.x, c, w * v3.x); c3.y = fmaf(c3.y, c, w * v3.y);
        c3.z = fmaf(c3.z, c, w * v3.z); c3.w = fmaf(c3.w, c, w * v3.w);
        m = mn;
    }
    // groups done; reconverge, then 2 merge rounds (xor 8, xor 16).
    // symmetric rescale: scale own state by c=exp(m-ms); partner's scaled
    // value (shfl of the already-scaled reg) uses partner's c = our co.
    __syncwarp();
#pragma unroll
    for (int off = 8; off <= 16; off <<= 1) {
        float mo = __shfl_xor_sync(0xffffffffu, m, off);
        float ms = fmaxf(m, mo);
        float c = __expf(m - ms);
        sum *= c;
        c0.x *= c; c0.y *= c; c0.z *= c; c0.w *= c;
        c1.x *= c; c1.y *= c; c1.z *= c; c1.w *= c;
        c2.x *= c; c2.y *= c; c2.z *= c; c2.w *= c;
        c3.x *= c; c3.y *= c; c3.z *= c; c3.w *= c;
        sum += __shfl_xor_sync(0xffffffffu, sum, off);
        c0.x += __shfl_xor_sync(0xffffffffu, c0.x, off);
        c0.y += __shfl_xor_sync(0xffffffffu, c0.y, off);
        c0.z += __shfl_xor_sync(0xffffffffu, c0.z, off);
        c0.w += __shfl_xor_sync(0xffffffffu, c0.w, off);
        c1.x += __shfl_xor_sync(0xffffffffu, c1.x, off);
        c1.y += __shfl_xor_sync(0xffffffffu, c1.y, off);
        c1.z += __shfl_xor_sync(0xffffffffu, c1.z, off);
        c1.w += __shfl_xor_sync(0xffffffffu, c1.w, off);
        c2.x += __shfl_xor_sync(0xffffffffu, c2.x, off);
        c2.y += __shfl_xor_sync(0xffffffffu, c2.y, off);
        c2.z += __shfl_xor_sync(0xffffffffu, c2.z, off);
        c2.w += __shfl_xor_sync(0xffffffffu, c2.w, off);
        c3.x += __shfl_xor_sync(0xffffffffu, c3.x, off);
        c3.y += __shfl_xor_sync(0xffffffffu, c3.y, off);
        c3.z += __shfl_xor_sync(0xffffffffu, c3.z, off);
        c3.w += __shfl_xor_sync(0xffffffffu, c3.w, off);
        m = ms;
    }
    if (grp == 0) {
        float inv = 1.f / (sum + 1e-16f);
        const float4* b4 = (const float4*)(bias + l8 * 16);
        float4 b0 = b4[0], b1 = b4[1], b2 = b4[2], b3 = b4[3];
        float4 o0, o1, o2, o3;
        o0.x = fmaf(c0.x, inv, b0.x); o0.y = fmaf(c0.y, inv, b0.y);
        o0.z = fmaf(c0.z, inv, b0.z); o0.w = fmaf(c0.w, inv, b0.w);
        o1.x = fmaf(c1.x, inv, b1.x); o1.y = fmaf(c1.y, inv, b1.y);
        o1.z = fmaf(c1.z, inv, b1.z); o1.w = fmaf(c1.w, inv, b1.w);
        o2.x = fmaf(c2.x, inv, b2.x); o2.y = fmaf(c2.y, inv, b2.y);
        o2.z = fmaf(c2.z, inv, b2.z); o2.w = fmaf(c2.w, inv, b2.w);
        o3.x = fmaf(c3.x, inv, b3.x); o3.y = fmaf(c3.y, inv, b3.y);
        o3.z = fmaf(c3.z, inv, b3.z); o3.w = fmaf(c3.w, inv, b3.w);
        float4* op = (float4*)(g_out + node * 128 + l8 * 16);
        op[0] = o0; op[1] = o1; op[2] = o2; op[3] = o3;
    }
}

// ---------------- BatchNorm stats + BN->GELU apply ----------------
__global__ void k_zero_cols() {
    g_colsum[threadIdx.x] = 0.f;
    g_colsq[threadIdx.x] = 0.f;
}

__global__ void k_bn() {
    int tid = threadIdx.x;
    int c4 = tid & 31;
    int rg = tid >> 5;
    float4 s = make_float4(0.f, 0.f, 0.f, 0.f);
    float4 q = make_float4(0.f, 0.f, 0.f, 0.f);
    for (int r = blockIdx.x * 8 + rg; r < NN; r += gridDim.x * 8) {
        float4 v = ((const float4*)g_out)[r * 32 + c4];
        s.x += v.x; s.y += v.y; s.z += v.z; s.w += v.w;
        q.x = fmaf(v.x, v.x, q.x); q.y = fmaf(v.y, v.y, q.y);
        q.z = fmaf(v.z, v.z, q.z); q.w = fmaf(v.w, v.w, q.w);
    }
    __shared__ float shs[8][32][4];
    __shared__ float shq[8][32][4];
    shs[rg][c4][0] = s.x; shs[rg][c4][1] = s.y; shs[rg][c4][2] = s.z; shs[rg][c4][3] = s.w;
    shq[rg][c4][0] = q.x; shq[rg][c4][1] = q.y; shq[rg][c4][2] = q.z; shq[rg][c4][3] = q.w;
    __syncthreads();
    if (tid < 128) {
        int col = tid;
        int cc4 = col >> 2, ce = col & 3;
        float ts = 0.f, tq = 0.f;
#pragma unroll
        for (int g = 0; g < 8; g++) {
            ts += shs[g][cc4][ce];
            tq += shq[g][cc4][ce];
        }
        atomicAdd(&g_colsum[col], ts);
        atomicAdd(&g_colsq[col], tq);
    }
}

// BN + erf-GELU; final layer -> fp32 d_out, else -> split bf16 for next GEMM
__global__ void k_bnapply(const float* __restrict__ gamma,
                          const float* __restrict__ beta,
                          float* __restrict__ dptr) {
    int i = blockIdx.x * 256 + threadIdx.x;  // over NN*32 float4s
    if (i >= NN * 32) return;
    int c4 = (i & 31) * 4;
    const float invN = 1.f / (float)NN;
    float4 v = ((const float4*)g_out)[i];
    float o[4];
    float vin[4] = {v.x, v.y, v.z, v.w};
#pragma unroll
    for (int c = 0; c < 4; c++) {
        float mu = g_colsum[c4 + c] * invN;
        float var = g_colsq[c4 + c] * invN - mu * mu;
        float y = gamma[c4 + c] * (vin[c] - mu) * rsqrtf(var + BNEPS) + beta[c4 + c];
        o[c] = 0.5f * y * (1.f + erff(y * 0.70710678118654752f));
    }
    if (dptr) {
        ((float4*)dptr)[i] = make_float4(o[0], o[1], o[2], o[3]);
    } else {
        uint32_t h0, l0, h1, l1;
        split2(o[0], o[1], h0, l0);
        split2(o[2], o[3], h1, l1);
        ((uint2*)g_xh)[i] = make_uint2(h0, h1);
        ((uint2*)g_xlo)[i] = make_uint2(l0, l1);
    }
}

// ---------------- launch ----------------
extern "C" void kernel_launch(void* const* d_in, const int* in_sizes, int n_in,
                              void* d_out, int out_size) {
    const float* x = (const float*)d_in[0];
    const int* ei = (const int*)d_in[1];
    const float* Wl = (const float*)d_in[2];
    const float* Wr = (const float*)d_in[3];
    const float* att = (const float*)d_in[4];
    const float* bias = (const float*)d_in[5];
    const float* gamma = (const float*)d_in[6];
    const float* beta = (const float*)d_in[7];
    float* outp = (float*)d_out;

    cudaFuncSetAttribute(k_gemm_mma, cudaFuncAttributeMaxDynamicSharedMemorySize, GEMM_SMEM);

    dim3 ggrid((NN + 63) / 64, 2);

    // launches 1-2: conversions; 3: detect+zero; 4: layer-0 GEMM (profiled slot)
    k_cvt_w<<<(3 * 2 * D * D + 255) / 256, 256>>>(Wl, Wr);
    k_cvt_x<<<(NN * 64 + 255) / 256, 256>>>(x);
    k_detect_zero<<<SB, 256>>>(ei);
    k_gemm_mma<<<ggrid, 256, GEMM_SMEM>>>(0);

    // CSR by dst
    k_hist<<<(NE + 255) / 256, 256>>>(ei);
    k_part<<<SB, 256>>>();
    k_scanpart<<<1, 256>>>();
    k_off<<<SB, 256>>>();
    k_scatter<<<(NE + 255) / 256, 256>>>(ei);

    for (int l = 0; l < 3; l++) {
        if (l > 0) k_gemm_mma<<<ggrid, 256, GEMM_SMEM>>>(l);
        k_node<<<(NN + 1) / 2, 64>>>(att + l * D, bias + l * D);
        k_zero_cols<<<1, 128>>>();
        k_bn<<<296, 256>>>();
        float* dst = (l == 2) ? outp : nullptr;
        k_bnapply<<<(NN * 32 + 255) / 256, 256>>>(gamma + l * D, beta + l * D, dst);
    }
}

// round 10
// speedup vs baseline: 1.2400x; 1.2400x over previous
#include <cuda_runtime.h>
#include <cuda_bf16.h>
#include <math.h>
#include <cstdint>

#define NN 50000
#define NE 800000
#define D  128
#define NEG 0.2f
#define BNEPS 1e-5f
#define SB 196   // scan blocks (196*256 = 50176 >= NN)

// ---------------- static device scratch (no allocations allowed) ----------------
__device__ float g_xl[NN * D];
__device__ float g_xr[NN * D];
__device__ float g_out[NN * D];
__device__ __nv_bfloat16 g_xh[NN * D];
__device__ __nv_bfloat16 g_xlo[NN * D];
__device__ __nv_bfloat16 g_whi[3 * 2 * D * D];   // W^T per layer/matrix: [lm][n][k]
__device__ __nv_bfloat16 g_wlo[3 * 2 * D * D];
__device__ int   g_srcs[NE];
__device__ int   g_off[NN + 1];
__device__ int   g_cur[NN];
__device__ int   g_cnt[NN];
__device__ int   g_part[256];
__device__ float g_colsum[D];
__device__ float g_colsq[D];
__device__ int   g_is64;

// ---------------- edge dtype probe + counter zero (fused) ----------------
__global__ void k_detect_zero(const int* __restrict__ w) {
    int i = blockIdx.x * 256 + threadIdx.x;
    if (i < NN) g_cnt[i] = 0;
    if (i == 0) {
        int allz = 1;
        for (int j = 1; j < 64; j += 2)
            if (w[j] != 0) allz = 0;
        g_is64 = allz;
    }
}

__device__ __forceinline__ int edge_at(const int* __restrict__ w, int pos, int is64) {
    return is64 ? w[(long long)pos * 2] : w[pos];
}

// ---------------- CSR build ----------------
__global__ void k_hist(const int* __restrict__ ei) {
    int e = blockIdx.x * 256 + threadIdx.x;
    if (e < NE) atomicAdd(&g_cnt[edge_at(ei, NE + e, g_is64)], 1);
}

__global__ void k_part() {
    __shared__ int sh[256];
    int tid = threadIdx.x;
    int i = blockIdx.x * 256 + tid;
    int v = (i < NN) ? g_cnt[i] : 0;
    sh[tid] = v;
    __syncthreads();
    for (int o = 128; o > 0; o >>= 1) {
        if (tid < o) sh[tid] += sh[tid + o];
        __syncthreads();
    }
    if (tid == 0) g_part[blockIdx.x] = sh[0];
}

__global__ void k_scanpart() {
    __shared__ int sh[256];
    int tid = threadIdx.x;
    int v = (tid < SB) ? g_part[tid] : 0;
    sh[tid] = v;
    __syncthreads();
    for (int o = 1; o < 256; o <<= 1) {
        int t = (tid >= o) ? sh[tid - o] : 0;
        __syncthreads();
        sh[tid] += t;
        __syncthreads();
    }
    g_part[tid] = sh[tid] - v;
}

__global__ void k_off() {
    __shared__ int sh[256];
    int tid = threadIdx.x;
    int i = blockIdx.x * 256 + tid;
    int v = (i < NN) ? g_cnt[i] : 0;
    sh[tid] = v;
    __syncthreads();
    for (int o = 1; o < 256; o <<= 1) {
        int t = (tid >= o) ? sh[tid - o] : 0;
        __syncthreads();
        sh[tid] += t;
        __syncthreads();
    }
    int excl = sh[tid] - v + g_part[blockIdx.x];
    if (i < NN) {
        g_off[i] = excl;
        g_cur[i] = excl;
        if (i == NN - 1) g_off[NN] = excl + v;
    }
}

__global__ void k_scatter(const int* __restrict__ ei) {
    int e = blockIdx.x * 256 + threadIdx.x;
    if (e < NE) {
        int is64 = g_is64;
        int src = edge_at(ei, e, is64);
        int dst = edge_at(ei, NE + e, is64);
        int pos = atomicAdd(&g_cur[dst], 1);
        g_srcs[pos] = src;
    }
}

// ---------------- conversions (fp32 -> split bf16) ----------------
__device__ __forceinline__ void split2(float a, float b, uint32_t& hi, uint32_t& lo) {
    __nv_bfloat16 ha = __float2bfloat16(a);
    __nv_bfloat16 hb = __float2bfloat16(b);
    __nv_bfloat16 la = __float2bfloat16(a - __bfloat162float(ha));
    __nv_bfloat16 lb = __float2bfloat16(b - __bfloat162float(hb));
    hi = (uint32_t)__bfloat16_as_ushort(ha) | ((uint32_t)__bfloat16_as_ushort(hb) << 16);
    lo = (uint32_t)__bfloat16_as_ushort(la) | ((uint32_t)__bfloat16_as_ushort(lb) << 16);
}

// W^T split: wt[lm][n][k] = W[l][k][n]   (lm = l*2+m; m: 0=Wl, 1=Wr)
__global__ void k_cvt_w(const float* __restrict__ Wl, const float* __restrict__ Wr) {
    int idx = blockIdx.x * 256 + threadIdx.x;
    if (idx >= 3 * 2 * D * D) return;
    int lm = idx >> 14, r = idx & 16383;
    int n = r >> 7, k = r & 127;
    int l = lm >> 1, m = lm & 1;
    const float* W = m ? Wr : Wl;
    float v = W[l * D * D + k * D + n];
    __nv_bfloat16 h = __float2bfloat16(v);
    __nv_bfloat16 lo = __float2bfloat16(v - __bfloat162float(h));
    g_whi[idx] = h;
    g_wlo[idx] = lo;
}

__global__ void k_cvt_x(const float* __restrict__ x) {
    int i = blockIdx.x * 256 + threadIdx.x;  // over NN*64 float2 groups
    if (i >= NN * 64) return;
    float2 v = ((const float2*)x)[i];
    uint32_t hi, lo;
    split2(v.x, v.y, hi, lo);
    ((uint32_t*)g_xh)[i] = hi;
    ((uint32_t*)g_xlo)[i] = lo;
}

// ---------------- tensor-core dual GEMM: smem + ldmatrix + mma.sync ----------------
__device__ __forceinline__ void mma16816(float* c, const uint32_t* a, const uint32_t* b) {
    asm volatile(
        "mma.sync.aligned.m16n8k16.row.col.f32.bf16.bf16.f32 "
        "{%0,%1,%2,%3}, {%4,%5,%6,%7}, {%8,%9}, {%0,%1,%2,%3};"
        : "+f"(c[0]), "+f"(c[1]), "+f"(c[2]), "+f"(c[3])
        : "r"(a[0]), "r"(a[1]), "r"(a[2]), "r"(a[3]), "r"(b[0]), "r"(b[1]));
}

__device__ __forceinline__ void ldsm4(uint32_t* r, uint32_t addr) {
    asm volatile(
        "ldmatrix.sync.aligned.m8n8.x4.shared.b16 {%0,%1,%2,%3}, [%4];"
        : "=r"(r[0]), "=r"(r[1]), "=r"(r[2]), "=r"(r[3]) : "r"(addr));
}

// smem: A_hi[128][256B] @0, A_lo @32KB, B tiles @64KB (Wl_hi, Wl_lo, Wr_hi, Wr_lo)
// row = 256B = 16 chunks of 16B; swizzle: chunk c stored at c ^ (row & 7)
#define GEMM_SMEM 196608

__global__ void __launch_bounds__(512, 1) k_gemm_mma(int l) {
    extern __shared__ __align__(16) char sm[];
    int tid = threadIdx.x;
    int row0 = blockIdx.x * 128;

    // stage A (x_hi, x_lo): 128 rows x 16 chunks
    for (int i = tid; i < 2048; i += 512) {
        int r = i >> 4, c = i & 15;
        int gr = row0 + r;
        uint4 vh = make_uint4(0, 0, 0, 0), vl = make_uint4(0, 0, 0, 0);
        if (gr < NN) {
            vh = *(const uint4*)(g_xh + gr * D + c * 8);
            vl = *(const uint4*)(g_xlo + gr * D + c * 8);
        }
        int sc = c ^ (r & 7);
        *(uint4*)(sm + r * 256 + sc * 16) = vh;
        *(uint4*)(sm + 32768 + r * 256 + sc * 16) = vl;
    }
    // stage B: 4 tiles (Wl_hi, Wl_lo, Wr_hi, Wr_lo), each 128 n-rows x 16 chunks
    for (int i = tid; i < 8192; i += 512) {
        int tile = i >> 11, j = i & 2047;
        int n = j >> 4, c = j & 15;
        int mm = tile >> 1;
        const __nv_bfloat16* src = (tile & 1) ? g_wlo : g_whi;
        uint4 v = *(const uint4*)(src + ((l * 2 + mm) * D + n) * D + c * 8);
        int sc = c ^ (n & 7);
        *(uint4*)(sm + 65536 + tile * 32768 + n * 256 + sc * 16) = v;
    }
    __syncthreads();

    int wid = tid >> 5, lane = tid & 31;
    int rg = wid & 3;          // row group: rows rg*32 .. rg*32+31
    int cg = wid >> 2;         // col group: 0,1 -> xl ; 2,3 -> xr
    int m = cg >> 1;
    int colbase = (cg & 1) * 64;
    uint32_t sbase = (uint32_t)__cvta_generic_to_shared(sm);
    uint32_t sA_h = sbase;
    uint32_t sA_l = sbase + 32768;
    uint32_t sB_h = sbase + 65536 + (uint32_t)(m * 2) * 32768u;
    uint32_t sB_l = sB_h + 32768;

    float acc[2][8][4];
#pragma unroll
    for (int mt = 0; mt < 2; mt++)
#pragma unroll
        for (int nt = 0; nt < 8; nt++)
#pragma unroll
            for (int q = 0; q < 4; q++) acc[mt][nt][q] = 0.f;

    // ldmatrix lane address components
    int a_r = (lane & 7) + ((lane >> 3) & 1) * 8;  // mat0/2: rows 0-7, mat1/3: rows 8-15
    int a_c = lane >> 4;                           // mat0/1: k0 chunk, mat2/3: k8 chunk
    int b_n = (lane & 7) + (lane >> 4) * 8;        // mat0/1: n0-7, mat2/3: n8-15
    int b_c = (lane >> 3) & 1;                     // mat0/2: k0 chunk, mat1/3: k8 chunk

#pragma unroll
    for (int ks = 0; ks < 8; ks++) {
        uint32_t ah[2][4], al[2][4];
#pragma unroll
        for (int mt = 0; mt < 2; mt++) {
            int r = rg * 32 + mt * 16 + a_r;
            int c = 2 * ks + a_c;
            uint32_t off = (uint32_t)(r * 256 + ((c ^ (r & 7)) << 4));
            ldsm4(ah[mt], sA_h + off);
            ldsm4(al[mt], sA_l + off);
        }
#pragma unroll
        for (int ng = 0; ng < 4; ng++) {
            int n = colbase + ng * 16 + b_n;
            int c = 2 * ks + b_c;
            uint32_t off = (uint32_t)(n * 256 + ((c ^ (n & 7)) << 4));
            uint32_t bh[4], bl[4];
            ldsm4(bh, sB_h + off);
            ldsm4(bl, sB_l + off);
#pragma unroll
            for (int mt = 0; mt < 2; mt++) {
                mma16816(acc[mt][2 * ng], ah[mt], &bh[0]);
                mma16816(acc[mt][2 * ng], ah[mt], &bl[0]);
                mma16816(acc[mt][2 * ng], al[mt], &bh[0]);
                mma16816(acc[mt][2 * ng + 1], ah[mt], &bh[2]);
                mma16816(acc[mt][2 * ng + 1], ah[mt], &bl[2]);
                mma16816(acc[mt][2 * ng + 1], al[mt], &bh[2]);
            }
        }
    }

    float* dst = m ? g_xr : g_xl;
    int g = lane >> 2, t = lane & 3;
#pragma unroll
    for (int mt = 0; mt < 2; mt++) {
#pragma unroll
        for (int nt = 0; nt < 8; nt++) {
            int r0 = row0 + rg * 32 + mt * 16 + g;
            int cc = colbase + nt * 8 + 2 * t;
            if (r0 < NN)
                *(float2*)(dst + r0 * D + cc) = make_float2(acc[mt][nt][0], acc[mt][nt][1]);
            if (r0 + 8 < NN)
                *(float2*)(dst + (r0 + 8) * D + cc) = make_float2(acc[mt][nt][2], acc[mt][nt][3]);
        }
    }
}

// ---------------- per-node GATv2: 16-lane groups, 2 edges in flight, prefetched ----------------
__device__ __forceinline__ float lrelu(float z) {
    return z > 0.f ? z : NEG * z;
}

__global__ void __launch_bounds__(256) k_node(const float* __restrict__ att,
                                              const float* __restrict__ bias) {
    int node = blockIdx.x * 8 + (threadIdx.x >> 5);
    if (node >= NN) return;
    int lane = threadIdx.x & 31;
    int l16 = lane & 15;
    int grp = lane >> 4;
    const unsigned gmask = 0xFFFFu << (grp << 4);
    int beg = g_off[node], end = g_off[node + 1];

    const float4* xr4 = (const float4*)(g_xr + node * 128 + l16 * 8);
    float4 xr0 = xr4[0], xr1 = xr4[1];
    const float4* at4 = (const float4*)(att + l16 * 8);
    float4 a0 = at4[0], a1 = at4[1];

    float m = -1e30f, sum = 0.f;
    float4 acc0 = make_float4(0.f, 0.f, 0.f, 0.f);
    float4 acc1 = make_float4(0.f, 0.f, 0.f, 0.f);

    // software pipeline: load edge p's row before processing, prefetch p+2
    // during the compute/shuffle of p so the LDG overlaps the shfl chain.
    int p = beg + grp;
    float4 v0 = make_float4(0.f, 0.f, 0.f, 0.f);
    float4 v1 = make_float4(0.f, 0.f, 0.f, 0.f);
    if (p < end) {
        const float4* v4 = (const float4*)(g_xl + g_srcs[p] * 128 + l16 * 8);
        v0 = v4[0];
        v1 = v4[1];
    }
    for (; p < end; p += 2) {
        // prefetch next edge for this group
        float4 n0, n1;
        int pn = p + 2;
        if (pn < end) {
            const float4* n4 = (const float4*)(g_xl + g_srcs[pn] * 128 + l16 * 8);
            n0 = n4[0];
            n1 = n4[1];
        }
        float d = lrelu(v0.x + xr0.x) * a0.x;
        d = fmaf(lrelu(v0.y + xr0.y), a0.y, d);
        d = fmaf(lrelu(v0.z + xr0.z), a0.z, d);
        d = fmaf(lrelu(v0.w + xr0.w), a0.w, d);
        d = fmaf(lrelu(v1.x + xr1.x), a1.x, d);
        d = fmaf(lrelu(v1.y + xr1.y), a1.y, d);
        d = fmaf(lrelu(v1.z + xr1.z), a1.z, d);
        d = fmaf(lrelu(v1.w + xr1.w), a1.w, d);
#pragma unroll
        for (int o = 1; o < 16; o <<= 1) d += __shfl_xor_sync(gmask, d, o);
        float mn = fmaxf(m, d);
        float c = __expf(m - mn);
        float w = __expf(d - mn);
        sum = sum * c + w;
        acc0.x = fmaf(acc0.x, c, w * v0.x);
        acc0.y = fmaf(acc0.y, c, w * v0.y);
        acc0.z = fmaf(acc0.z, c, w * v0.z);
        acc0.w = fmaf(acc0.w, c, w * v0.w);
        acc1.x = fmaf(acc1.x, c, w * v1.x);
        acc1.y = fmaf(acc1.y, c, w * v1.y);
        acc1.z = fmaf(acc1.z, c, w * v1.z);
        acc1.w = fmaf(acc1.w, c, w * v1.w);
        m = mn;
        if (pn < end) {
            v0 = n0;
            v1 = n1;
        }
    }
    __syncwarp();
    float mo = __shfl_xor_sync(0xffffffffu, m, 16);
    float so = __shfl_xor_sync(0xffffffffu, sum, 16);
    float ms = fmaxf(m, mo);
    float cme = __expf(m - ms);
    float sum_t = fmaf(so, __expf(mo - ms), sum * cme);
    acc0.x *= cme; acc0.y *= cme; acc0.z *= cme; acc0.w *= cme;
    acc1.x *= cme; acc1.y *= cme; acc1.z *= cme; acc1.w *= cme;
    acc0.x += __shfl_xor_sync(0xffffffffu, acc0.x, 16);
    acc0.y += __shfl_xor_sync(0xffffffffu, acc0.y, 16);
    acc0.z += __shfl_xor_sync(0xffffffffu, acc0.z, 16);
    acc0.w += __shfl_xor_sync(0xffffffffu, acc0.w, 16);
    acc1.x += __shfl_xor_sync(0xffffffffu, acc1.x, 16);
    acc1.y += __shfl_xor_sync(0xffffffffu, acc1.y, 16);
    acc1.z += __shfl_xor_sync(0xffffffffu, acc1.z, 16);
    acc1.w += __shfl_xor_sync(0xffffffffu, acc1.w, 16);
    if (grp == 0) {
        float inv = 1.f / (sum_t + 1e-16f);
        const float4* b4 = (const float4*)(bias + l16 * 8);
        float4 b0 = b4[0], b1 = b4[1];
        float4 o0, o1;
        o0.x = fmaf(acc0.x, inv, b0.x);
        o0.y = fmaf(acc0.y, inv, b0.y);
        o0.z = fmaf(acc0.z, inv, b0.z);
        o0.w = fmaf(acc0.w, inv, b0.w);
        o1.x = fmaf(acc1.x, inv, b1.x);
        o1.y = fmaf(acc1.y, inv, b1.y);
        o1.z = fmaf(acc1.z, inv, b1.z);
        o1.w = fmaf(acc1.w, inv, b1.w);
        float4* op = (float4*)(g_out + node * 128 + l16 * 8);
        op[0] = o0;
        op[1] = o1;
    }
}

// ---------------- BatchNorm stats + BN->GELU apply ----------------
__global__ void k_zero_cols() {
    g_colsum[threadIdx.x] = 0.f;
    g_colsq[threadIdx.x] = 0.f;
}

__global__ void k_bn() {
    int tid = threadIdx.x;
    int c4 = tid & 31;
    int rg = tid >> 5;
    float4 s = make_float4(0.f, 0.f, 0.f, 0.f);
    float4 q = make_float4(0.f, 0.f, 0.f, 0.f);
    for (int r = blockIdx.x * 8 + rg; r < NN; r += gridDim.x * 8) {
        float4 v = ((const float4*)g_out)[r * 32 + c4];
        s.x += v.x; s.y += v.y; s.z += v.z; s.w += v.w;
        q.x = fmaf(v.x, v.x, q.x); q.y = fmaf(v.y, v.y, q.y);
        q.z = fmaf(v.z, v.z, q.z); q.w = fmaf(v.w, v.w, q.w);
    }
    __shared__ float shs[8][32][4];
    __shared__ float shq[8][32][4];
    shs[rg][c4][0] = s.x; shs[rg][c4][1] = s.y; shs[rg][c4][2] = s.z; shs[rg][c4][3] = s.w;
    shq[rg][c4][0] = q.x; shq[rg][c4][1] = q.y; shq[rg][c4][2] = q.z; shq[rg][c4][3] = q.w;
    __syncthreads();
    if (tid < 128) {
        int col = tid;
        int cc4 = col >> 2, ce = col & 3;
        float ts = 0.f, tq = 0.f;
#pragma unroll
        for (int g = 0; g < 8; g++) {
            ts += shs[g][cc4][ce];
            tq += shq[g][cc4][ce];
        }
        atomicAdd(&g_colsum[col], ts);
        atomicAdd(&g_colsq[col], tq);
    }
}

// BN + erf-GELU; final layer -> fp32 d_out, else -> split bf16 for next GEMM
__global__ void k_bnapply(const float* __restrict__ gamma,
                          const float* __restrict__ beta,
                          float* __restrict__ dptr) {
    int i = blockIdx.x * 256 + threadIdx.x;  // over NN*32 float4s
    if (i >= NN * 32) return;
    int c4 = (i & 31) * 4;
    const float invN = 1.f / (float)NN;
    float4 v = ((const float4*)g_out)[i];
    float o[4];
    float vin[4] = {v.x, v.y, v.z, v.w};
#pragma unroll
    for (int c = 0; c < 4; c++) {
        float mu = g_colsum[c4 + c] * invN;
        float var = g_colsq[c4 + c] * invN - mu * mu;
        float y = gamma[c4 + c] * (vin[c] - mu) * rsqrtf(var + BNEPS) + beta[c4 + c];
        o[c] = 0.5f * y * (1.f + erff(y * 0.70710678118654752f));
    }
    if (dptr) {
        ((float4*)dptr)[i] = make_float4(o[0], o[1], o[2], o[3]);
    } else {
        uint32_t h0, l0, h1, l1;
        split2(o[0], o[1], h0, l0);
        split2(o[2], o[3], h1, l1);
        ((uint2*)g_xh)[i] = make_uint2(h0, h1);
        ((uint2*)g_xlo)[i] = make_uint2(l0, l1);
    }
}

// ---------------- launch ----------------
extern "C" void kernel_launch(void* const* d_in, const int* in_sizes, int n_in,
                              void* d_out, int out_size) {
    const float* x = (const float*)d_in[0];
    const int* ei = (const int*)d_in[1];
    const float* Wl = (const float*)d_in[2];
    const float* Wr = (const float*)d_in[3];
    const float* att = (const float*)d_in[4];
    const float* bias = (const float*)d_in[5];
    const float* gamma = (const float*)d_in[6];
    const float* beta = (const float*)d_in[7];
    float* outp = (float*)d_out;

    cudaFuncSetAttribute(k_gemm_mma, cudaFuncAttributeMaxDynamicSharedMemorySize, GEMM_SMEM);

    const int gemm_blocks = (NN + 127) / 128;

    // launches 1-2: conversions; 3: detect+zero; 4: layer-0 GEMM (profiled slot)
    k_cvt_w<<<(3 * 2 * D * D + 255) / 256, 256>>>(Wl, Wr);
    k_cvt_x<<<(NN * 64 + 255) / 256, 256>>>(x);
    k_detect_zero<<<SB, 256>>>(ei);
    k_gemm_mma<<<gemm_blocks, 512, GEMM_SMEM>>>(0);

    // CSR by dst
    k_hist<<<(NE + 255) / 256, 256>>>(ei);
    k_part<<<SB, 256>>>();
    k_scanpart<<<1, 256>>>();
    k_off<<<SB, 256>>>();
    k_scatter<<<(NE + 255) / 256, 256>>>(ei);

    for (int l = 0; l < 3; l++) {
        if (l > 0) k_gemm_mma<<<gemm_blocks, 512, GEMM_SMEM>>>(l);
        k_node<<<(NN + 7) / 8, 256>>>(att + l * D, bias + l * D);
        k_zero_cols<<<1, 128>>>();
        k_bn<<<296, 256>>>();
        float* dst = (l == 2) ? outp : nullptr;
        k_bnapply<<<(NN * 32 + 255) / 256, 256>>>(gamma + l * D, beta + l * D, dst);
    }
}

// round 12
// speedup vs baseline: 1.4118x; 1.1386x over previous
#include <cuda_runtime.h>
#include <cuda_bf16.h>
#include <math.h>
#include <cstdint>

#define NN 50000
#define NE 800000
#define D  128
#define NEG 0.2f
#define BNEPS 1e-5f
#define SB 196   // scan blocks (196*256 = 50176 >= NN)

// ---------------- static device scratch (no allocations allowed) ----------------
__device__ float g_xl[NN * D];
__device__ float g_xr[NN * D];
__device__ float g_out[NN * D];
__device__ __nv_bfloat16 g_xh[NN * D];
__device__ __nv_bfloat16 g_xlo[NN * D];
__device__ __nv_bfloat16 g_whi[3 * 2 * D * D];   // W^T per layer/matrix: [lm][n][k]
__device__ __nv_bfloat16 g_wlo[3 * 2 * D * D];
__device__ int   g_srcs[NE];
__device__ int   g_off[NN + 1];
__device__ int   g_cur[NN];
__device__ int   g_cnt[NN];
__device__ int   g_part[256];
__device__ float g_colsum[D];
__device__ float g_colsq[D];
__device__ int   g_is64;

// ---------------- edge dtype probe + counter zero (fused) ----------------
__global__ void k_detect_zero(const int* __restrict__ w) {
    int i = blockIdx.x * 256 + threadIdx.x;
    if (i < NN) g_cnt[i] = 0;
    if (i == 0) {
        int allz = 1;
        for (int j = 1; j < 64; j += 2)
            if (w[j] != 0) allz = 0;
        g_is64 = allz;
    }
}

__device__ __forceinline__ int edge_at(const int* __restrict__ w, int pos, int is64) {
    return is64 ? w[(long long)pos * 2] : w[pos];
}

// ---------------- CSR build ----------------
__global__ void k_hist(const int* __restrict__ ei) {
    int e = blockIdx.x * 256 + threadIdx.x;
    if (e < NE) atomicAdd(&g_cnt[edge_at(ei, NE + e, g_is64)], 1);
}

__global__ void k_part() {
    __shared__ int sh[256];
    int tid = threadIdx.x;
    int i = blockIdx.x * 256 + tid;
    int v = (i < NN) ? g_cnt[i] : 0;
    sh[tid] = v;
    __syncthreads();
    for (int o = 128; o > 0; o >>= 1) {
        if (tid < o) sh[tid] += sh[tid + o];
        __syncthreads();
    }
    if (tid == 0) g_part[blockIdx.x] = sh[0];
}

__global__ void k_scanpart() {
    __shared__ int sh[256];
    int tid = threadIdx.x;
    int v = (tid < SB) ? g_part[tid] : 0;
    sh[tid] = v;
    __syncthreads();
    for (int o = 1; o < 256; o <<= 1) {
        int t = (tid >= o) ? sh[tid - o] : 0;
        __syncthreads();
        sh[tid] += t;
        __syncthreads();
    }
    g_part[tid] = sh[tid] - v;
}

__global__ void k_off() {
    __shared__ int sh[256];
    int tid = threadIdx.x;
    int i = blockIdx.x * 256 + tid;
    int v = (i < NN) ? g_cnt[i] : 0;
    sh[tid] = v;
    __syncthreads();
    for (int o = 1; o < 256; o <<= 1) {
        int t = (tid >= o) ? sh[tid - o] : 0;
        __syncthreads();
        sh[tid] += t;
        __syncthreads();
    }
    int excl = sh[tid] - v + g_part[blockIdx.x];
    if (i < NN) {
        g_off[i] = excl;
        g_cur[i] = excl;
        if (i == NN - 1) g_off[NN] = excl + v;
    }
}

__global__ void k_scatter(const int* __restrict__ ei) {
    int e = blockIdx.x * 256 + threadIdx.x;
    if (e < NE) {
        int is64 = g_is64;
        int src = edge_at(ei, e, is64);
        int dst = edge_at(ei, NE + e, is64);
        int pos = atomicAdd(&g_cur[dst], 1);
        g_srcs[pos] = src;
    }
}

// ---------------- conversions (fp32 -> split bf16) ----------------
__device__ __forceinline__ void split2(float a, float b, uint32_t& hi, uint32_t& lo) {
    __nv_bfloat16 ha = __float2bfloat16(a);
    __nv_bfloat16 hb = __float2bfloat16(b);
    __nv_bfloat16 la = __float2bfloat16(a - __bfloat162float(ha));
    __nv_bfloat16 lb = __float2bfloat16(b - __bfloat162float(hb));
    hi = (uint32_t)__bfloat16_as_ushort(ha) | ((uint32_t)__bfloat16_as_ushort(hb) << 16);
    lo = (uint32_t)__bfloat16_as_ushort(la) | ((uint32_t)__bfloat16_as_ushort(lb) << 16);
}

// W^T split: wt[lm][n][k] = W[l][k][n]   (lm = l*2+m; m: 0=Wl, 1=Wr)
__global__ void k_cvt_w(const float* __restrict__ Wl, const float* __restrict__ Wr) {
    int idx = blockIdx.x * 256 + threadIdx.x;
    if (idx >= 3 * 2 * D * D) return;
    int lm = idx >> 14, r = idx & 16383;
    int n = r >> 7, k = r & 127;
    int l = lm >> 1, m = lm & 1;
    const float* W = m ? Wr : Wl;
    float v = W[l * D * D + k * D + n];
    __nv_bfloat16 h = __float2bfloat16(v);
    __nv_bfloat16 lo = __float2bfloat16(v - __bfloat162float(h));
    g_whi[idx] = h;
    g_wlo[idx] = lo;
}

__global__ void k_cvt_x(const float* __restrict__ x) {
    int i = blockIdx.x * 256 + threadIdx.x;  // over NN*64 float2 groups
    if (i >= NN * 64) return;
    float2 v = ((const float2*)x)[i];
    uint32_t hi, lo;
    split2(v.x, v.y, hi, lo);
    ((uint32_t*)g_xh)[i] = hi;
    ((uint32_t*)g_xlo)[i] = lo;
}

// ---------------- tensor-core dual GEMM: cp.async + ldmatrix + mma.sync ----------------
__device__ __forceinline__ void mma16816(float* c, const uint32_t* a, const uint32_t* b) {
    asm volatile(
        "mma.sync.aligned.m16n8k16.row.col.f32.bf16.bf16.f32 "
        "{%0,%1,%2,%3}, {%4,%5,%6,%7}, {%8,%9}, {%0,%1,%2,%3};"
        : "+f"(c[0]), "+f"(c[1]), "+f"(c[2]), "+f"(c[3])
        : "r"(a[0]), "r"(a[1]), "r"(a[2]), "r"(a[3]), "r"(b[0]), "r"(b[1]));
}

__device__ __forceinline__ void ldsm4(uint32_t* r, uint32_t addr) {
    asm volatile(
        "ldmatrix.sync.aligned.m8n8.x4.shared.b16 {%0,%1,%2,%3}, [%4];"
        : "=r"(r[0]), "=r"(r[1]), "=r"(r[2]), "=r"(r[3]) : "r"(addr));
}

__device__ __forceinline__ void cp16(uint32_t dst, const void* src, int sz) {
    asm volatile("cp.async.cg.shared.global [%0], [%1], 16, %2;"
                 :: "r"(dst), "l"(src), "r"(sz));
}
#define CP_COMMIT() asm volatile("cp.async.commit_group;")
#define CP_WAIT0()  asm volatile("cp.async.wait_group 0;" ::: "memory")

// smem: A_hi[128][256B] @0, A_lo @32KB, B tiles @64KB (Wl_hi, Wl_lo, Wr_hi, Wr_lo)
// row = 256B = 16 chunks of 16B; swizzle: chunk c stored at c ^ (row & 7)
#define GEMM_SMEM 196608

__global__ void __launch_bounds__(512, 1) k_gemm_mma(int l) {
    extern __shared__ __align__(16) char sm[];
    int tid = threadIdx.x;
    int row0 = blockIdx.x * 128;
    uint32_t sbase = (uint32_t)__cvta_generic_to_shared(sm);

    // stage A (x_hi, x_lo): 128 rows x 16 chunks via cp.async (zero-fill OOB)
    for (int i = tid; i < 2048; i += 512) {
        int r = i >> 4, c = i & 15;
        int gr = row0 + r;
        int sz = (gr < NN) ? 16 : 0;
        uint32_t soff = (uint32_t)(r * 256 + ((c ^ (r & 7)) << 4));
        cp16(sbase + soff, g_xh + gr * D + c * 8, sz);
        cp16(sbase + 32768 + soff, g_xlo + gr * D + c * 8, sz);
    }
    // stage B: 4 tiles (Wl_hi, Wl_lo, Wr_hi, Wr_lo), each 128 n-rows x 16 chunks
    for (int i = tid; i < 8192; i += 512) {
        int tile = i >> 11, j = i & 2047;
        int n = j >> 4, c = j & 15;
        int mm = tile >> 1;
        const __nv_bfloat16* src = (tile & 1) ? g_wlo : g_whi;
        uint32_t soff = (uint32_t)(65536 + tile * 32768 + n * 256 + ((c ^ (n & 7)) << 4));
        cp16(sbase + soff, src + ((l * 2 + mm) * D + n) * D + c * 8, 16);
    }
    CP_COMMIT();
    CP_WAIT0();
    __syncthreads();

    int wid = tid >> 5, lane = tid & 31;
    int rg = wid & 3;          // row group: rows rg*32 .. rg*32+31
    int cg = wid >> 2;         // col group: 0,1 -> xl ; 2,3 -> xr
    int m = cg >> 1;
    int colbase = (cg & 1) * 64;
    uint32_t sA_h = sbase;
    uint32_t sA_l = sbase + 32768;
    uint32_t sB_h = sbase + 65536 + (uint32_t)(m * 2) * 32768u;
    uint32_t sB_l = sB_h + 32768;

    float acc[2][8][4];
#pragma unroll
    for (int mt = 0; mt < 2; mt++)
#pragma unroll
        for (int nt = 0; nt < 8; nt++)
#pragma unroll
            for (int q = 0; q < 4; q++) acc[mt][nt][q] = 0.f;

    // ldmatrix lane address components
    int a_r = (lane & 7) + ((lane >> 3) & 1) * 8;
    int a_c = lane >> 4;
    int b_n = (lane & 7) + (lane >> 4) * 8;
    int b_c = (lane >> 3) & 1;

#pragma unroll
    for (int ks = 0; ks < 8; ks++) {
        uint32_t ah[2][4], al[2][4];
#pragma unroll
        for (int mt = 0; mt < 2; mt++) {
            int r = rg * 32 + mt * 16 + a_r;
            int c = 2 * ks + a_c;
            uint32_t off = (uint32_t)(r * 256 + ((c ^ (r & 7)) << 4));
            ldsm4(ah[mt], sA_h + off);
            ldsm4(al[mt], sA_l + off);
        }
#pragma unroll
        for (int ng = 0; ng < 4; ng++) {
            int n = colbase + ng * 16 + b_n;
            int c = 2 * ks + b_c;
            uint32_t off = (uint32_t)(n * 256 + ((c ^ (n & 7)) << 4));
            uint32_t bh[4], bl[4];
            ldsm4(bh, sB_h + off);
            ldsm4(bl, sB_l + off);
            // term-outer order: same-acc dependency gap = 4 HMMA
            mma16816(acc[0][2 * ng], ah[0], &bh[0]);
            mma16816(acc[0][2 * ng + 1], ah[0], &bh[2]);
            mma16816(acc[1][2 * ng], ah[1], &bh[0]);
            mma16816(acc[1][2 * ng + 1], ah[1], &bh[2]);
            mma16816(acc[0][2 * ng], ah[0], &bl[0]);
            mma16816(acc[0][2 * ng + 1], ah[0], &bl[2]);
            mma16816(acc[1][2 * ng], ah[1], &bl[0]);
            mma16816(acc[1][2 * ng + 1], ah[1], &bl[2]);
            mma16816(acc[0][2 * ng], al[0], &bh[0]);
            mma16816(acc[0][2 * ng + 1], al[0], &bh[2]);
            mma16816(acc[1][2 * ng], al[1], &bh[0]);
            mma16816(acc[1][2 * ng + 1], al[1], &bh[2]);
        }
    }

    float* dst = m ? g_xr : g_xl;
    int g = lane >> 2, t = lane & 3;
#pragma unroll
    for (int mt = 0; mt < 2; mt++) {
#pragma unroll
        for (int nt = 0; nt < 8; nt++) {
            int r0 = row0 + rg * 32 + mt * 16 + g;
            int cc = colbase + nt * 8 + 2 * t;
            if (r0 < NN)
                *(float2*)(dst + r0 * D + cc) = make_float2(acc[mt][nt][0], acc[mt][nt][1]);
            if (r0 + 8 < NN)
                *(float2*)(dst + (r0 + 8) * D + cc) = make_float2(acc[mt][nt][2], acc[mt][nt][3]);
        }
    }
}

// ---------------- per-node GATv2: 16-lane groups, 2 edges in flight ----------------
__device__ __forceinline__ float lrelu(float z) {
    return z > 0.f ? z : NEG * z;
}

__global__ void __launch_bounds__(64) k_node(const float* __restrict__ att,
                                             const float* __restrict__ bias) {
    // fused: block 0 zeroes the BN column stats (read later by k_bn)
    if (blockIdx.x == 0) {
        int t = threadIdx.x;
        g_colsum[t] = 0.f;
        g_colsum[t + 64] = 0.f;
        g_colsq[t] = 0.f;
        g_colsq[t + 64] = 0.f;
    }
    int node = blockIdx.x * 2 + (threadIdx.x >> 5);
    if (node >= NN) return;
    int lane = threadIdx.x & 31;
    int l16 = lane & 15;
    int grp = lane >> 4;
    const unsigned gmask = 0xFFFFu << (grp << 4);
    int beg = g_off[node], end = g_off[node + 1];

    const float4* xr4 = (const float4*)(g_xr + node * 128 + l16 * 8);
    float4 xr0 = xr4[0], xr1 = xr4[1];
    const float4* at4 = (const float4*)(att + l16 * 8);
    float4 a0 = at4[0], a1 = at4[1];

    float m = -1e30f, sum = 0.f;
    float4 acc0 = make_float4(0.f, 0.f, 0.f, 0.f);
    float4 acc1 = make_float4(0.f, 0.f, 0.f, 0.f);

    for (int p = beg + grp; p < end; p += 2) {
        int s = g_srcs[p];
        const float4* v4 = (const float4*)(g_xl + s * 128 + l16 * 8);
        float4 v0 = v4[0], v1 = v4[1];
        float d = lrelu(v0.x + xr0.x) * a0.x;
        d = fmaf(lrelu(v0.y + xr0.y), a0.y, d);
        d = fmaf(lrelu(v0.z + xr0.z), a0.z, d);
        d = fmaf(lrelu(v0.w + xr0.w), a0.w, d);
        d = fmaf(lrelu(v1.x + xr1.x), a1.x, d);
        d = fmaf(lrelu(v1.y + xr1.y), a1.y, d);
        d = fmaf(lrelu(v1.z + xr1.z), a1.z, d);
        d = fmaf(lrelu(v1.w + xr1.w), a1.w, d);
#pragma unroll
        for (int o = 1; o < 16; o <<= 1) d += __shfl_xor_sync(gmask, d, o);
        float mn = fmaxf(m, d);
        float c = __expf(m - mn);
        float w = __expf(d - mn);
        sum = sum * c + w;
        acc0.x = fmaf(acc0.x, c, w * v0.x);
        acc0.y = fmaf(acc0.y, c, w * v0.y);
        acc0.z = fmaf(acc0.z, c, w * v0.z);
        acc0.w = fmaf(acc0.w, c, w * v0.w);
        acc1.x = fmaf(acc1.x, c, w * v1.x);
        acc1.y = fmaf(acc1.y, c, w * v1.y);
        acc1.z = fmaf(acc1.z, c, w * v1.z);
        acc1.w = fmaf(acc1.w, c, w * v1.w);
        m = mn;
    }
    __syncwarp();
    float mo = __shfl_xor_sync(0xffffffffu, m, 16);
    float so = __shfl_xor_sync(0xffffffffu, sum, 16);
    float ms = fmaxf(m, mo);
    float cme = __expf(m - ms);
    float sum_t = fmaf(so, __expf(mo - ms), sum * cme);
    acc0.x *= cme; acc0.y *= cme; acc0.z *= cme; acc0.w *= cme;
    acc1.x *= cme; acc1.y *= cme; acc1.z *= cme; acc1.w *= cme;
    acc0.x += __shfl_xor_sync(0xffffffffu, acc0.x, 16);
    acc0.y += __shfl_xor_sync(0xffffffffu, acc0.y, 16);
    acc0.z += __shfl_xor_sync(0xffffffffu, acc0.z, 16);
    acc0.w += __shfl_xor_sync(0xffffffffu, acc0.w, 16);
    acc1.x += __shfl_xor_sync(0xffffffffu, acc1.x, 16);
    acc1.y += __shfl_xor_sync(0xffffffffu, acc1.y, 16);
    acc1.z += __shfl_xor_sync(0xffffffffu, acc1.z, 16);
    acc1.w += __shfl_xor_sync(0xffffffffu, acc1.w, 16);
    if (grp == 0) {
        float inv = 1.f / (sum_t + 1e-16f);
        const float4* b4 = (const float4*)(bias + l16 * 8);
        float4 b0 = b4[0], b1 = b4[1];
        float4 o0, o1;
        o0.x = fmaf(acc0.x, inv, b0.x);
        o0.y = fmaf(acc0.y, inv, b0.y);
        o0.z = fmaf(acc0.z, inv, b0.z);
        o0.w = fmaf(acc0.w, inv, b0.w);
        o1.x = fmaf(acc1.x, inv, b1.x);
        o1.y = fmaf(acc1.y, inv, b1.y);
        o1.z = fmaf(acc1.z, inv, b1.z);
        o1.w = fmaf(acc1.w, inv, b1.w);
        float4* op = (float4*)(g_out + node * 128 + l16 * 8);
        op[0] = o0;
        op[1] = o1;
    }
}

// ---------------- BatchNorm stats + BN->GELU apply ----------------
__global__ void k_bn() {
    int tid = threadIdx.x;
    int c4 = tid & 31;
    int rg = tid >> 5;
    float4 s = make_float4(0.f, 0.f, 0.f, 0.f);
    float4 q = make_float4(0.f, 0.f, 0.f, 0.f);
    for (int r = blockIdx.x * 8 + rg; r < NN; r += gridDim.x * 8) {
        float4 v = ((const float4*)g_out)[r * 32 + c4];
        s.x += v.x; s.y += v.y; s.z += v.z; s.w += v.w;
        q.x = fmaf(v.x, v.x, q.x); q.y = fmaf(v.y, v.y, q.y);
        q.z = fmaf(v.z, v.z, q.z); q.w = fmaf(v.w, v.w, q.w);
    }
    __shared__ float shs[8][32][4];
    __shared__ float shq[8][32][4];
    shs[rg][c4][0] = s.x; shs[rg][c4][1] = s.y; shs[rg][c4][2] = s.z; shs[rg][c4][3] = s.w;
    shq[rg][c4][0] = q.x; shq[rg][c4][1] = q.y; shq[rg][c4][2] = q.z; shq[rg][c4][3] = q.w;
    __syncthreads();
    if (tid < 128) {
        int col = tid;
        int cc4 = col >> 2, ce = col & 3;
        float ts = 0.f, tq = 0.f;
#pragma unroll
        for (int g = 0; g < 8; g++) {
            ts += shs[g][cc4][ce];
            tq += shq[g][cc4][ce];
        }
        atomicAdd(&g_colsum[col], ts);
        atomicAdd(&g_colsq[col], tq);
    }
}

// BN + erf-GELU; final layer -> fp32 d_out, else -> split bf16 for next GEMM
__global__ void k_bnapply(const float* __restrict__ gamma,
                          const float* __restrict__ beta,
                          float* __restrict__ dptr) {
    int i = blockIdx.x * 256 + threadIdx.x;  // over NN*32 float4s
    if (i >= NN * 32) return;
    int c4 = (i & 31) * 4;
    const float invN = 1.f / (float)NN;
    float4 v = ((const float4*)g_out)[i];
    float o[4];
    float vin[4] = {v.x, v.y, v.z, v.w};
#pragma unroll
    for (int c = 0; c < 4; c++) {
        float mu = g_colsum[c4 + c] * invN;
        float var = g_colsq[c4 + c] * invN - mu * mu;
        float y = gamma[c4 + c] * (vin[c] - mu) * rsqrtf(var + BNEPS) + beta[c4 + c];
        o[c] = 0.5f * y * (1.f + erff(y * 0.70710678118654752f));
    }
    if (dptr) {
        ((float4*)dptr)[i] = make_float4(o[0], o[1], o[2], o[3]);
    } else {
        uint32_t h0, l0, h1, l1;
        split2(o[0], o[1], h0, l0);
        split2(o[2], o[3], h1, l1);
        ((uint2*)g_xh)[i] = make_uint2(h0, h1);
        ((uint2*)g_xlo)[i] = make_uint2(l0, l1);
    }
}

// ---------------- launch ----------------
extern "C" void kernel_launch(void* const* d_in, const int* in_sizes, int n_in,
                              void* d_out, int out_size) {
    const float* x = (const float*)d_in[0];
    const int* ei = (const int*)d_in[1];
    const float* Wl = (const float*)d_in[2];
    const float* Wr = (const float*)d_in[3];
    const float* att = (const float*)d_in[4];
    const float* bias = (const float*)d_in[5];
    const float* gamma = (const float*)d_in[6];
    const float* beta = (const float*)d_in[7];
    float* outp = (float*)d_out;

    cudaFuncSetAttribute(k_gemm_mma, cudaFuncAttributeMaxDynamicSharedMemorySize, GEMM_SMEM);

    const int gemm_blocks = (NN + 127) / 128;

    // launches 1-2: conversions; 3: detect+zero; 4: layer-0 GEMM (profiled slot)
    k_cvt_w<<<(3 * 2 * D * D + 255) / 256, 256>>>(Wl, Wr);
    k_cvt_x<<<(NN * 64 + 255) / 256, 256>>>(x);
    k_detect_zero<<<SB, 256>>>(ei);
    k_gemm_mma<<<gemm_blocks, 512, GEMM_SMEM>>>(0);

    // CSR by dst
    k_hist<<<(NE + 255) / 256, 256>>>(ei);
    k_part<<<SB, 256>>>();
    k_scanpart<<<1, 256>>>();
    k_off<<<SB, 256>>>();
    k_scatter<<<(NE + 255) / 256, 256>>>(ei);

    for (int l = 0; l < 3; l++) {
        if (l > 0) k_gemm_mma<<<gemm_blocks, 512, GEMM_SMEM>>>(l);
        k_node<<<(NN + 1) / 2, 64>>>(att + l * D, bias + l * D);
        k_bn<<<296, 256>>>();
        float* dst = (l == 2) ? outp : nullptr;
        k_bnapply<<<(NN * 32 + 255) / 256, 256>>>(gamma + l * D, beta + l * D, dst);
    }
}

// round 13
// speedup vs baseline: 1.4579x; 1.0326x over previous
#include <cuda_runtime.h>
#include <cuda_bf16.h>
#include <math.h>
#include <cstdint>

#define NN 50000
#define NE 800000
#define D  128
#define NEG 0.2f
#define BNEPS 1e-5f
#define SB 196   // scan blocks (196*256 = 50176 >= NN)

// ---------------- static device scratch (no allocations allowed) ----------------
__device__ float g_xl[NN * D];
__device__ float g_xr[NN * D];
__device__ float g_out[NN * D];
__device__ __nv_bfloat16 g_whi[3 * 2 * D * D];   // W^T per layer/matrix: [lm][n][k]
__device__ __nv_bfloat16 g_wlo[3 * 2 * D * D];
__device__ int   g_srcs[NE];
__device__ int   g_off[NN + 1];
__device__ int   g_cur[NN];
__device__ int   g_cnt[NN];
__device__ int   g_part[256];
__device__ float g_colsum[D];
__device__ float g_colsq[D];
__device__ int   g_is64;

// ---------------- edge dtype probe + counter zero (fused) ----------------
__global__ void k_detect_zero(const int* __restrict__ w) {
    int i = blockIdx.x * 256 + threadIdx.x;
    if (i < NN) g_cnt[i] = 0;
    if (i == 0) {
        int allz = 1;
        for (int j = 1; j < 64; j += 2)
            if (w[j] != 0) allz = 0;
        g_is64 = allz;
    }
}

__device__ __forceinline__ int edge_at(const int* __restrict__ w, int pos, int is64) {
    return is64 ? w[(long long)pos * 2] : w[pos];
}

// ---------------- CSR build ----------------
__global__ void k_hist(const int* __restrict__ ei) {
    int e = blockIdx.x * 256 + threadIdx.x;
    if (e < NE) atomicAdd(&g_cnt[edge_at(ei, NE + e, g_is64)], 1);
}

__global__ void k_part() {
    __shared__ int sh[256];
    int tid = threadIdx.x;
    int i = blockIdx.x * 256 + tid;
    int v = (i < NN) ? g_cnt[i] : 0;
    sh[tid] = v;
    __syncthreads();
    for (int o = 128; o > 0; o >>= 1) {
        if (tid < o) sh[tid] += sh[tid + o];
        __syncthreads();
    }
    if (tid == 0) g_part[blockIdx.x] = sh[0];
}

__global__ void k_scanpart() {
    __shared__ int sh[256];
    int tid = threadIdx.x;
    int v = (tid < SB) ? g_part[tid] : 0;
    sh[tid] = v;
    __syncthreads();
    for (int o = 1; o < 256; o <<= 1) {
        int t = (tid >= o) ? sh[tid - o] : 0;
        __syncthreads();
        sh[tid] += t;
        __syncthreads();
    }
    g_part[tid] = sh[tid] - v;
}

__global__ void k_off() {
    __shared__ int sh[256];
    int tid = threadIdx.x;
    int i = blockIdx.x * 256 + tid;
    int v = (i < NN) ? g_cnt[i] : 0;
    sh[tid] = v;
    __syncthreads();
    for (int o = 1; o < 256; o <<= 1) {
        int t = (tid >= o) ? sh[tid - o] : 0;
        __syncthreads();
        sh[tid] += t;
        __syncthreads();
    }
    int excl = sh[tid] - v + g_part[blockIdx.x];
    if (i < NN) {
        g_off[i] = excl;
        g_cur[i] = excl;
        if (i == NN - 1) g_off[NN] = excl + v;
    }
}

__global__ void k_scatter(const int* __restrict__ ei) {
    int e = blockIdx.x * 256 + threadIdx.x;
    if (e < NE) {
        int is64 = g_is64;
        int src = edge_at(ei, e, is64);
        int dst = edge_at(ei, NE + e, is64);
        int pos = atomicAdd(&g_cur[dst], 1);
        g_srcs[pos] = src;
    }
}

// ---------------- conversions (fp32 -> split bf16) ----------------
__device__ __forceinline__ void split2(float a, float b, uint32_t& hi, uint32_t& lo) {
    __nv_bfloat16 ha = __float2bfloat16(a);
    __nv_bfloat16 hb = __float2bfloat16(b);
    __nv_bfloat16 la = __float2bfloat16(a - __bfloat162float(ha));
    __nv_bfloat16 lb = __float2bfloat16(b - __bfloat162float(hb));
    hi = (uint32_t)__bfloat16_as_ushort(ha) | ((uint32_t)__bfloat16_as_ushort(hb) << 16);
    lo = (uint32_t)__bfloat16_as_ushort(la) | ((uint32_t)__bfloat16_as_ushort(lb) << 16);
}

// W^T split: wt[lm][n][k] = W[l][k][n]   (lm = l*2+m; m: 0=Wl, 1=Wr)
__global__ void k_cvt_w(const float* __restrict__ Wl, const float* __restrict__ Wr) {
    int idx = blockIdx.x * 256 + threadIdx.x;
    if (idx >= 3 * 2 * D * D) return;
    int lm = idx >> 14, r = idx & 16383;
    int n = r >> 7, k = r & 127;
    int l = lm >> 1, m = lm & 1;
    const float* W = m ? Wr : Wl;
    float v = W[l * D * D + k * D + n];
    __nv_bfloat16 h = __float2bfloat16(v);
    __nv_bfloat16 lo = __float2bfloat16(v - __bfloat162float(h));
    g_whi[idx] = h;
    g_wlo[idx] = lo;
}

// ---------------- tensor-core dual GEMM: fused BN/GELU/split A-stage + cp.async B ----------------
__device__ __forceinline__ void mma16816(float* c, const uint32_t* a, const uint32_t* b) {
    asm volatile(
        "mma.sync.aligned.m16n8k16.row.col.f32.bf16.bf16.f32 "
        "{%0,%1,%2,%3}, {%4,%5,%6,%7}, {%8,%9}, {%0,%1,%2,%3};"
        : "+f"(c[0]), "+f"(c[1]), "+f"(c[2]), "+f"(c[3])
        : "r"(a[0]), "r"(a[1]), "r"(a[2]), "r"(a[3]), "r"(b[0]), "r"(b[1]));
}

__device__ __forceinline__ void ldsm4(uint32_t* r, uint32_t addr) {
    asm volatile(
        "ldmatrix.sync.aligned.m8n8.x4.shared.b16 {%0,%1,%2,%3}, [%4];"
        : "=r"(r[0]), "=r"(r[1]), "=r"(r[2]), "=r"(r[3]) : "r"(addr));
}

__device__ __forceinline__ void cp16(uint32_t dst, const void* src, int sz) {
    asm volatile("cp.async.cg.shared.global [%0], [%1], 16, %2;"
                 :: "r"(dst), "l"(src), "r"(sz));
}
#define CP_COMMIT() asm volatile("cp.async.commit_group;")
#define CP_WAIT0()  asm volatile("cp.async.wait_group 0;" ::: "memory")

// smem: A_hi[128][256B] @0, A_lo @32KB, B tiles @64KB (Wl_hi, Wl_lo, Wr_hi, Wr_lo),
// stats @192KB (scale[128], shift[128]).
// row = 256B = 16 chunks of 16B; swizzle: chunk c stored at c ^ (row & 7)
#define GEMM_SMEM (196608 + 1024)

// l==0: A rows come from xin (plain split). l>0: A rows = gelu(BN(g_out)) with
// stats from g_colsum/g_colsq and gamma/beta of layer l-1, then split.
__global__ void __launch_bounds__(512, 1) k_gemm_mma(int l, const float* __restrict__ xin,
                                                     const float* __restrict__ gamma,
                                                     const float* __restrict__ beta) {
    extern __shared__ __align__(16) char sm[];
    float* sstat = (float*)(sm + 196608);
    int tid = threadIdx.x;
    int row0 = blockIdx.x * 128;
    uint32_t sbase = (uint32_t)__cvta_generic_to_shared(sm);

    // B first (async, flies under A compute): 4 tiles, each 128 n-rows x 16 chunks
    for (int i = tid; i < 8192; i += 512) {
        int tile = i >> 11, j = i & 2047;
        int n = j >> 4, c = j & 15;
        int mm = tile >> 1;
        const __nv_bfloat16* src = (tile & 1) ? g_wlo : g_whi;
        uint32_t soff = (uint32_t)(65536 + tile * 32768 + n * 256 + ((c ^ (n & 7)) << 4));
        cp16(sbase + soff, src + ((l * 2 + mm) * D + n) * D + c * 8, 16);
    }
    CP_COMMIT();

    // BN stats -> smem (scale/shift per column)
    if (l > 0) {
        if (tid < 128) {
            const float invN = 1.f / (float)NN;
            float mu = g_colsum[tid] * invN;
            float var = g_colsq[tid] * invN - mu * mu;
            float sc = gamma[tid] * rsqrtf(var + BNEPS);
            sstat[tid] = sc;
            sstat[128 + tid] = beta[tid] - mu * sc;
        }
        __syncthreads();
    }

    // A stage: 128 rows x 16 chunks (8 elems each); fp32 in, BN/GELU (l>0), split2, STS
    const float* asrc = (l == 0) ? xin : g_out;
    for (int i = tid; i < 2048; i += 512) {
        int r = i >> 4, c = i & 15;
        int gr = row0 + r;
        uint4 hi = make_uint4(0, 0, 0, 0), lo = make_uint4(0, 0, 0, 0);
        if (gr < NN) {
            const float4* sp = (const float4*)(asrc + gr * D + c * 8);
            float4 va = sp[0], vb = sp[1];
            float e[8] = {va.x, va.y, va.z, va.w, vb.x, vb.y, vb.z, vb.w};
            if (l > 0) {
                int col = c * 8;
#pragma unroll
                for (int j = 0; j < 8; j++) {
                    float y = fmaf(e[j], sstat[col + j], sstat[128 + col + j]);
                    e[j] = 0.5f * y * (1.f + erff(y * 0.70710678118654752f));
                }
            }
            split2(e[0], e[1], hi.x, lo.x);
            split2(e[2], e[3], hi.y, lo.y);
            split2(e[4], e[5], hi.z, lo.z);
            split2(e[6], e[7], hi.w, lo.w);
        }
        uint32_t soff = (uint32_t)(r * 256 + ((c ^ (r & 7)) << 4));
        *(uint4*)(sm + soff) = hi;
        *(uint4*)(sm + 32768 + soff) = lo;
    }
    CP_WAIT0();
    __syncthreads();

    int wid = tid >> 5, lane = tid & 31;
    int rg = wid & 3;          // row group: rows rg*32 .. rg*32+31
    int cg = wid >> 2;         // col group: 0,1 -> xl ; 2,3 -> xr
    int m = cg >> 1;
    int colbase = (cg & 1) * 64;
    uint32_t sA_h = sbase;
    uint32_t sA_l = sbase + 32768;
    uint32_t sB_h = sbase + 65536 + (uint32_t)(m * 2) * 32768u;
    uint32_t sB_l = sB_h + 32768;

    float acc[2][8][4];
#pragma unroll
    for (int mt = 0; mt < 2; mt++)
#pragma unroll
        for (int nt = 0; nt < 8; nt++)
#pragma unroll
            for (int q = 0; q < 4; q++) acc[mt][nt][q] = 0.f;

    // ldmatrix lane address components
    int a_r = (lane & 7) + ((lane >> 3) & 1) * 8;
    int a_c = lane >> 4;
    int b_n = (lane & 7) + (lane >> 4) * 8;
    int b_c = (lane >> 3) & 1;

#pragma unroll
    for (int ks = 0; ks < 8; ks++) {
        uint32_t ah[2][4], al[2][4];
#pragma unroll
        for (int mt = 0; mt < 2; mt++) {
            int r = rg * 32 + mt * 16 + a_r;
            int c = 2 * ks + a_c;
            uint32_t off = (uint32_t)(r * 256 + ((c ^ (r & 7)) << 4));
            ldsm4(ah[mt], sA_h + off);
            ldsm4(al[mt], sA_l + off);
        }
#pragma unroll
        for (int ng = 0; ng < 4; ng++) {
            int n = colbase + ng * 16 + b_n;
            int c = 2 * ks + b_c;
            uint32_t off = (uint32_t)(n * 256 + ((c ^ (n & 7)) << 4));
            uint32_t bh[4], bl[4];
            ldsm4(bh, sB_h + off);
            ldsm4(bl, sB_l + off);
            // term-outer order: same-acc dependency gap = 4 HMMA
            mma16816(acc[0][2 * ng], ah[0], &bh[0]);
            mma16816(acc[0][2 * ng + 1], ah[0], &bh[2]);
            mma16816(acc[1][2 * ng], ah[1], &bh[0]);
            mma16816(acc[1][2 * ng + 1], ah[1], &bh[2]);
            mma16816(acc[0][2 * ng], ah[0], &bl[0]);
            mma16816(acc[0][2 * ng + 1], ah[0], &bl[2]);
            mma16816(acc[1][2 * ng], ah[1], &bl[0]);
            mma16816(acc[1][2 * ng + 1], ah[1], &bl[2]);
            mma16816(acc[0][2 * ng], al[0], &bh[0]);
            mma16816(acc[0][2 * ng + 1], al[0], &bh[2]);
            mma16816(acc[1][2 * ng], al[1], &bh[0]);
            mma16816(acc[1][2 * ng + 1], al[1], &bh[2]);
        }
    }

    float* dst = m ? g_xr : g_xl;
    int g = lane >> 2, t = lane & 3;
#pragma unroll
    for (int mt = 0; mt < 2; mt++) {
#pragma unroll
        for (int nt = 0; nt < 8; nt++) {
            int r0 = row0 + rg * 32 + mt * 16 + g;
            int cc = colbase + nt * 8 + 2 * t;
            if (r0 < NN)
                *(float2*)(dst + r0 * D + cc) = make_float2(acc[mt][nt][0], acc[mt][nt][1]);
            if (r0 + 8 < NN)
                *(float2*)(dst + (r0 + 8) * D + cc) = make_float2(acc[mt][nt][2], acc[mt][nt][3]);
        }
    }
}

// ---------------- per-node GATv2: 16-lane groups, 2 edges in flight ----------------
__device__ __forceinline__ float lrelu(float z) {
    return z > 0.f ? z : NEG * z;
}

__global__ void __launch_bounds__(64) k_node(const float* __restrict__ att,
                                             const float* __restrict__ bias) {
    // fused: block 0 zeroes the BN column stats (read later by k_bn)
    if (blockIdx.x == 0) {
        int t = threadIdx.x;
        g_colsum[t] = 0.f;
        g_colsum[t + 64] = 0.f;
        g_colsq[t] = 0.f;
        g_colsq[t + 64] = 0.f;
    }
    int node = blockIdx.x * 2 + (threadIdx.x >> 5);
    if (node >= NN) return;
    int lane = threadIdx.x & 31;
    int l16 = lane & 15;
    int grp = lane >> 4;
    const unsigned gmask = 0xFFFFu << (grp << 4);
    int beg = g_off[node], end = g_off[node + 1];

    const float4* xr4 = (const float4*)(g_xr + node * 128 + l16 * 8);
    float4 xr0 = xr4[0], xr1 = xr4[1];
    const float4* at4 = (const float4*)(att + l16 * 8);
    float4 a0 = at4[0], a1 = at4[1];

    float m = -1e30f, sum = 0.f;
    float4 acc0 = make_float4(0.f, 0.f, 0.f, 0.f);
    float4 acc1 = make_float4(0.f, 0.f, 0.f, 0.f);

    for (int p = beg + grp; p < end; p += 2) {
        int s = g_srcs[p];
        const float4* v4 = (const float4*)(g_xl + s * 128 + l16 * 8);
        float4 v0 = v4[0], v1 = v4[1];
        float d = lrelu(v0.x + xr0.x) * a0.x;
        d = fmaf(lrelu(v0.y + xr0.y), a0.y, d);
        d = fmaf(lrelu(v0.z + xr0.z), a0.z, d);
        d = fmaf(lrelu(v0.w + xr0.w), a0.w, d);
        d = fmaf(lrelu(v1.x + xr1.x), a1.x, d);
        d = fmaf(lrelu(v1.y + xr1.y), a1.y, d);
        d = fmaf(lrelu(v1.z + xr1.z), a1.z, d);
        d = fmaf(lrelu(v1.w + xr1.w), a1.w, d);
#pragma unroll
        for (int o = 1; o < 16; o <<= 1) d += __shfl_xor_sync(gmask, d, o);
        float mn = fmaxf(m, d);
        float c = __expf(m - mn);
        float w = __expf(d - mn);
        sum = sum * c + w;
        acc0.x = fmaf(acc0.x, c, w * v0.x);
        acc0.y = fmaf(acc0.y, c, w * v0.y);
        acc0.z = fmaf(acc0.z, c, w * v0.z);
        acc0.w = fmaf(acc0.w, c, w * v0.w);
        acc1.x = fmaf(acc1.x, c, w * v1.x);
        acc1.y = fmaf(acc1.y, c, w * v1.y);
        acc1.z = fmaf(acc1.z, c, w * v1.z);
        acc1.w = fmaf(acc1.w, c, w * v1.w);
        m = mn;
    }
    __syncwarp();
    float mo = __shfl_xor_sync(0xffffffffu, m, 16);
    float so = __shfl_xor_sync(0xffffffffu, sum, 16);
    float ms = fmaxf(m, mo);
    float cme = __expf(m - ms);
    float sum_t = fmaf(so, __expf(mo - ms), sum * cme);
    acc0.x *= cme; acc0.y *= cme; acc0.z *= cme; acc0.w *= cme;
    acc1.x *= cme; acc1.y *= cme; acc1.z *= cme; acc1.w *= cme;
    acc0.x += __shfl_xor_sync(0xffffffffu, acc0.x, 16);
    acc0.y += __shfl_xor_sync(0xffffffffu, acc0.y, 16);
    acc0.z += __shfl_xor_sync(0xffffffffu, acc0.z, 16);
    acc0.w += __shfl_xor_sync(0xffffffffu, acc0.w, 16);
    acc1.x += __shfl_xor_sync(0xffffffffu, acc1.x, 16);
    acc1.y += __shfl_xor_sync(0xffffffffu, acc1.y, 16);
    acc1.z += __shfl_xor_sync(0xffffffffu, acc1.z, 16);
    acc1.w += __shfl_xor_sync(0xffffffffu, acc1.w, 16);
    if (grp == 0) {
        float inv = 1.f / (sum_t + 1e-16f);
        const float4* b4 = (const float4*)(bias + l16 * 8);
        float4 b0 = b4[0], b1 = b4[1];
        float4 o0, o1;
        o0.x = fmaf(acc0.x, inv, b0.x);
        o0.y = fmaf(acc0.y, inv, b0.y);
        o0.z = fmaf(acc0.z, inv, b0.z);
        o0.w = fmaf(acc0.w, inv, b0.w);
        o1.x = fmaf(acc1.x, inv, b1.x);
        o1.y = fmaf(acc1.y, inv, b1.y);
        o1.z = fmaf(acc1.z, inv, b1.z);
        o1.w = fmaf(acc1.w, inv, b1.w);
        float4* op = (float4*)(g_out + node * 128 + l16 * 8);
        op[0] = o0;
        op[1] = o1;
    }
}

// ---------------- BatchNorm stats ----------------
__global__ void k_bn() {
    int tid = threadIdx.x;
    int c4 = tid & 31;
    int rg = tid >> 5;
    float4 s = make_float4(0.f, 0.f, 0.f, 0.f);
    float4 q = make_float4(0.f, 0.f, 0.f, 0.f);
    for (int r = blockIdx.x * 8 + rg; r < NN; r += gridDim.x * 8) {
        float4 v = ((const float4*)g_out)[r * 32 + c4];
        s.x += v.x; s.y += v.y; s.z += v.z; s.w += v.w;
        q.x = fmaf(v.x, v.x, q.x); q.y = fmaf(v.y, v.y, q.y);
        q.z = fmaf(v.z, v.z, q.z); q.w = fmaf(v.w, v.w, q.w);
    }
    __shared__ float shs[8][32][4];
    __shared__ float shq[8][32][4];
    shs[rg][c4][0] = s.x; shs[rg][c4][1] = s.y; shs[rg][c4][2] = s.z; shs[rg][c4][3] = s.w;
    shq[rg][c4][0] = q.x; shq[rg][c4][1] = q.y; shq[rg][c4][2] = q.z; shq[rg][c4][3] = q.w;
    __syncthreads();
    if (tid < 128) {
        int col = tid;
        int cc4 = col >> 2, ce = col & 3;
        float ts = 0.f, tq = 0.f;
#pragma unroll
        for (int g = 0; g < 8; g++) {
            ts += shs[g][cc4][ce];
            tq += shq[g][cc4][ce];
        }
        atomicAdd(&g_colsum[col], ts);
        atomicAdd(&g_colsq[col], tq);
    }
}

// final-layer BN + erf-GELU -> fp32 d_out
__global__ void k_bnapply(const float* __restrict__ gamma,
                          const float* __restrict__ beta,
                          float* __restrict__ dptr) {
    int i = blockIdx.x * 256 + threadIdx.x;  // over NN*32 float4s
    if (i >= NN * 32) return;
    int c4 = (i & 31) * 4;
    const float invN = 1.f / (float)NN;
    float4 v = ((const float4*)g_out)[i];
    float o[4];
    float vin[4] = {v.x, v.y, v.z, v.w};
#pragma unroll
    for (int c = 0; c < 4; c++) {
        float mu = g_colsum[c4 + c] * invN;
        float var = g_colsq[c4 + c] * invN - mu * mu;
        float y = gamma[c4 + c] * (vin[c] - mu) * rsqrtf(var + BNEPS) + beta[c4 + c];
        o[c] = 0.5f * y * (1.f + erff(y * 0.70710678118654752f));
    }
    ((float4*)dptr)[i] = make_float4(o[0], o[1], o[2], o[3]);
}

// ---------------- launch ----------------
extern "C" void kernel_launch(void* const* d_in, const int* in_sizes, int n_in,
                              void* d_out, int out_size) {
    const float* x = (const float*)d_in[0];
    const int* ei = (const int*)d_in[1];
    const float* Wl = (const float*)d_in[2];
    const float* Wr = (const float*)d_in[3];
    const float* att = (const float*)d_in[4];
    const float* bias = (const float*)d_in[5];
    const float* gamma = (const float*)d_in[6];
    const float* beta = (const float*)d_in[7];
    float* outp = (float*)d_out;

    cudaFuncSetAttribute(k_gemm_mma, cudaFuncAttributeMaxDynamicSharedMemorySize, GEMM_SMEM);

    const int gemm_blocks = (NN + 127) / 128;

    // launches 1-3: cvt_w, detect+zero, hist; 4: layer-0 GEMM (profiled slot)
    k_cvt_w<<<(3 * 2 * D * D + 255) / 256, 256>>>(Wl, Wr);
    k_detect_zero<<<SB, 256>>>(ei);
    k_hist<<<(NE + 255) / 256, 256>>>(ei);
    k_gemm_mma<<<gemm_blocks, 512, GEMM_SMEM>>>(0, x, nullptr, nullptr);

    // CSR by dst (remaining stages)
    k_part<<<SB, 256>>>();
    k_scanpart<<<1, 256>>>();
    k_off<<<SB, 256>>>();
    k_scatter<<<(NE + 255) / 256, 256>>>(ei);

    for (int l = 0; l < 3; l++) {
        if (l > 0)
            k_gemm_mma<<<gemm_blocks, 512, GEMM_SMEM>>>(l, nullptr,
                                                        gamma + (l - 1) * D,
                                                        beta + (l - 1) * D);
        k_node<<<(NN + 1) / 2, 64>>>(att + l * D, bias + l * D);
        k_bn<<<296, 256>>>();
    }
    // final BN+GELU -> output
    k_bnapply<<<(NN * 32 + 255) / 256, 256>>>(gamma + 2 * D, beta + 2 * D, outp);
}